// round 9
// baseline (speedup 1.0000x reference)
#include <cuda_runtime.h>
#include <cstdint>

// Problem constants
#define LL 2
#define BB 16
#define TT 512
#define HH 12
#define NL 4096   // (1+1)^12 leaves
#define NC 1000
#define NCHUNK 16 // token chunks per batch
#define TOKC 32   // tokens per chunk

// Scratch: [chunk][batch][leaf]  (4 MB)
__device__ float g_part[NCHUNK * BB * NL];

// ---- f32x2 helpers ---------------------------------------------------------
__device__ __forceinline__ unsigned long long pk2(float x, float y) {
    unsigned long long r;
    asm("mov.b64 %0, {%1, %2};" : "=l"(r) : "f"(x), "f"(y));
    return r;
}
__device__ __forceinline__ void fma2(unsigned long long& d,
                                     unsigned long long a,
                                     unsigned long long b) {
    asm("fma.rn.f32x2 %0, %1, %2, %0;" : "+l"(d) : "l"(a), "l"(b));
}
__device__ __forceinline__ void upk2(unsigned long long v, float& lo, float& hi) {
    asm("mov.b64 {%0, %1}, %2;" : "=f"(lo), "=f"(hi) : "l"(v));
}

// ---- smem/TMA helpers ------------------------------------------------------
__device__ __forceinline__ uint32_t smem_u32(const void* p) {
    uint32_t a;
    asm("{ .reg .u64 t; cvta.to.shared.u64 t, %1; cvt.u32.u64 %0, t; }"
        : "=r"(a) : "l"(p));
    return a;
}
__device__ __forceinline__ void mbar_init(uint32_t mbar, uint32_t count) {
    asm volatile("mbarrier.init.shared.b64 [%0], %1;" :: "r"(mbar), "r"(count)
                 : "memory");
}
__device__ __forceinline__ void mbar_expect_tx(uint32_t mbar, uint32_t bytes) {
    asm volatile("mbarrier.arrive.expect_tx.shared.b64 _, [%0], %1;"
                 :: "r"(mbar), "r"(bytes) : "memory");
}
__device__ __forceinline__ void mbar_wait(uint32_t mbar, uint32_t parity) {
    uint32_t done;
    asm volatile(
        "{\n\t"
        ".reg .pred p;\n\t"
        "mbarrier.try_wait.parity.acquire.cta.shared::cta.b64 p, [%1], %2;\n\t"
        "selp.b32 %0, 1, 0, p;\n\t"
        "}"
        : "=r"(done) : "r"(mbar), "r"(parity) : "memory");
    if (!done) {
        asm volatile(
            "{\n\t"
            ".reg .pred P1;\n\t"
            "W_%=:\n\t"
            "mbarrier.try_wait.parity.acquire.cta.shared::cta.b64 P1, [%0], %1, 0x989680;\n\t"
            "@P1 bra.uni D_%=;\n\t"
            "bra.uni W_%=;\n\t"
            "D_%=:\n\t"
            "}"
            :: "r"(mbar), "r"(parity) : "memory");
    }
}
__device__ __forceinline__ void bulk_g2s(uint32_t dst, const void* src,
                                         uint32_t bytes, uint32_t mbar) {
    asm volatile(
        "cp.async.bulk.shared::cta.global.mbarrier::complete_tx::bytes "
        "[%0], [%1], %2, [%3];"
        :: "r"(dst), "l"(src), "r"(bytes), "r"(mbar) : "memory");
}

// ---------------------------------------------------------------------------
// Kernel 1: per-(batch, token-chunk) partial mean-leaf vectors, disjoint STG.
// grid = B * NCHUNK = 256 blocks, 256 threads. Also zeroes `out`.
// ---------------------------------------------------------------------------
__global__ __launch_bounds__(256) void leaf_kernel(
    const float* __restrict__ x, const float* __restrict__ cuts,
    float* __restrict__ out)
{
    const int tid = threadIdx.x;
    const int gid = blockIdx.x * 256 + tid;    // 65536 >= 16000
    if (gid < BB * NC) out[gid] = 0.f;

    const int b     = blockIdx.x >> 4;
    const int chunk = blockIdx.x & 15;

    __shared__ float P[TOKC * 128];            // [tok][half*64 + u]  (16 KB)
    __shared__ float sx[TOKC * 12];
    __shared__ float sc[12];

    if (tid < 12) sc[tid] = cuts[tid];

    const float* xl = x + (size_t)(LL - 1) * BB * TT * HH
                        + ((size_t)b * TT + (size_t)chunk * TOKC) * HH;
    for (int i = tid; i < TOKC * 12; i += 256) sx[i] = xl[i];
    __syncthreads();

    // Phase A: factorized half-leaf products (8 contiguous outputs per task)
    {
        const int half = (tid >> 3) & 1;
        const int g    = tid & 7;
        const float* cr = sc + half * 6;
        const float c0 = cr[0], c1 = cr[1], c2 = cr[2];
        const float c3 = cr[3], c4 = cr[4], c5 = cr[5];
#pragma unroll
        for (int t2 = 0; t2 < 2; t2++) {
            const int tok = (tid >> 4) + t2 * 16;
            const float* xr = sx + tok * 12 + half * 6;
            const float x0 = xr[0], x1 = xr[1], x2 = xr[2];
            const float x3 = xr[3], x4 = xr[4], x5 = xr[5];
            const float F0 = (g & 4) ? fmaf(2.f, x0, -c0) : x0;
            const float F1 = (g & 2) ? fmaf(2.f, x1, -c1) : x1;
            const float F2 = (g & 1) ? fmaf(2.f, x2, -c2) : x2;
            const float p  = F0 * F1 * F2;
            const float b3 = fmaf(2.f, x3, -c3);
            const float a4 = x4, b4 = fmaf(2.f, x4, -c4);
            const float a5 = x5, b5 = fmaf(2.f, x5, -c5);
            const float m00 = a4 * a5, m01 = a4 * b5;
            const float m10 = b4 * a5, m11 = b4 * b5;
            const float q0 = p * x3, q1 = p * b3;
            float* dst = P + tok * 128 + half * 64 + g * 8;
            *(float4*)dst       = make_float4(q0 * m00, q0 * m01, q0 * m10, q0 * m11);
            *(float4*)(dst + 4) = make_float4(q1 * m00, q1 * m01, q1 * m10, q1 * m11);
        }
    }
    __syncthreads();

    // Phase B: rank-1 accumulation
    const int w = tid >> 5, lane = tid & 31;
    unsigned long long acc2[4][2];
#pragma unroll
    for (int p = 0; p < 4; p++) { acc2[p][0] = 0ull; acc2[p][1] = 0ull; }

#pragma unroll 4
    for (int tok = 0; tok < TOKC; tok++) {
        const float* Pr = P + tok * 128;
        const ulonglong2* ph = (const ulonglong2*)(Pr + 8 * w);
        const ulonglong2 h0 = ph[0];
        const ulonglong2 h1 = ph[1];
        const float plo0 = Pr[64 + lane];
        const float plo1 = Pr[64 + lane + 32];
        const unsigned long long pl0 = pk2(plo0, plo0);
        const unsigned long long pl1 = pk2(plo1, plo1);
        fma2(acc2[0][0], h0.x, pl0); fma2(acc2[0][1], h0.x, pl1);
        fma2(acc2[1][0], h0.y, pl0); fma2(acc2[1][1], h0.y, pl1);
        fma2(acc2[2][0], h1.x, pl0); fma2(acc2[2][1], h1.x, pl1);
        fma2(acc2[3][0], h1.y, pl0); fma2(acc2[3][1], h1.y, pl1);
    }

    const float s = 1.f / (float)TT;
    float* dst = g_part + ((size_t)(chunk * BB + b)) * NL;
#pragma unroll
    for (int p = 0; p < 4; p++) {
        float u0v0, u1v0, u0v1, u1v1;
        upk2(acc2[p][0], u0v0, u1v0);
        upk2(acc2[p][1], u0v1, u1v1);
        const int u0 = 8 * w + 2 * p;
        dst[u0 * 64 + lane]            = u0v0 * s;
        dst[u0 * 64 + lane + 32]       = u0v1 * s;
        dst[(u0 + 1) * 64 + lane]      = u1v0 * s;
        dst[(u0 + 1) * 64 + lane + 32] = u1v1 * s;
    }
}

// ---------------------------------------------------------------------------
// Kernel 2: out[16,1000] += avg[16,4096] @ score[4096,1000].
// grid = (64 row-chunks, 4 col-tiles) = 256 CTAs, 256 threads.
// CTA tile: 64 rows x 256 cols (last tile 232 cols).
// Score streamed with cp.async.bulk (TMA): 8 rows x ~1KB per stage,
// 4 slots, mbarrier completion, parity flip on slot reuse.
// Thread owns 1 column x all 16 batches (8 packed f32x2 accumulators).
// ---------------------------------------------------------------------------
#define G_LCH   64
#define G_CTW   256            // cols per tile (floats)
#define R_STG   8              // rows per stage
#define NSLOT   4
#define NITER   (G_LCH / R_STG)  // 8

__global__ __launch_bounds__(256) void gemm_out_kernel(
    const float* __restrict__ score, float* __restrict__ out)
{
    __shared__ __align__(128) float sS[NSLOT * R_STG * G_CTW];  // 32 KB
    __shared__ float sA[G_LCH * 16];                            // 4 KB [l][b]
    __shared__ __align__(8) unsigned long long mbar_store[NSLOT];

    const int tid = threadIdx.x;
    const int l0  = blockIdx.x * G_LCH;
    const int c0  = blockIdx.y * G_CTW;
    const int wbytes = (c0 + G_CTW <= NC) ? (G_CTW * 4) : ((NC - c0) * 4); // 1024 or 928
    const uint32_t sS_base = smem_u32(sS);
    const uint32_t mb0 = smem_u32(mbar_store);

    if (tid == 0) {
#pragma unroll
        for (int s = 0; s < NSLOT; s++) mbar_init(mb0 + 8 * s, 1);
        asm volatile("fence.proxy.async.shared::cta;" ::: "memory");
    }
    __syncthreads();

    // Stage issue (single thread): stage it -> slot it&3
    auto issue_stage = [&](int it) {
        const int slot = it & (NSLOT - 1);
        const uint32_t mb = mb0 + 8 * slot;
        mbar_expect_tx(mb, (uint32_t)(R_STG * wbytes));
        const char* src0 = (const char*)score
            + (size_t)(l0 + it * R_STG) * (NC * 4) + (size_t)c0 * 4;
#pragma unroll
        for (int r = 0; r < R_STG; r++) {
            bulk_g2s(sS_base + (uint32_t)((slot * R_STG + r) * G_CTW * 4),
                     src0 + (size_t)r * (NC * 4), (uint32_t)wbytes, mb);
        }
    };

    if (tid == 0) {
#pragma unroll
        for (int s = 0; s < NSLOT; s++) issue_stage(s);
    }

    // Build sA by reducing the 16 L2-hot chunk partials (float4):
    // 256 tasks = 16 batches x 16 leaf-quads, one per thread.
    {
        const int bb = tid >> 4;          // batch 0..15
        const int lq = tid & 15;          // leaf quad 0..15
        const float4* p = (const float4*)(g_part + (size_t)bb * NL + l0) + lq;
        float4 v = make_float4(0.f, 0.f, 0.f, 0.f);
#pragma unroll
        for (int ch = 0; ch < NCHUNK; ch++) {
            const float4 t = p[(size_t)ch * (BB * NL / 4)];
            v.x += t.x; v.y += t.y; v.z += t.z; v.w += t.w;
        }
        sA[(lq * 4 + 0) * 16 + bb] = v.x;
        sA[(lq * 4 + 1) * 16 + bb] = v.y;
        sA[(lq * 4 + 2) * 16 + bb] = v.z;
        sA[(lq * 4 + 3) * 16 + bb] = v.w;
    }
    __syncthreads();

    unsigned long long acc[8];
#pragma unroll
    for (int p = 0; p < 8; p++) acc[p] = 0ull;

    const int c = c0 + tid;

    // Main loop: wait stage, compute 8 rows, sync, refill freed slot.
    for (int it = 0; it < NITER; it++) {
        const int slot = it & (NSLOT - 1);
        const uint32_t parity = (it >> 2) & 1;
        mbar_wait(mb0 + 8 * slot, parity);

        const float* sSs = sS + slot * (R_STG * G_CTW) + tid;
        const float* sAs = sA + (it * R_STG) * 16;
#pragma unroll
        for (int r = 0; r < R_STG; r++) {
            const float sv = sSs[r * G_CTW];
            const unsigned long long ss = pk2(sv, sv);
            const ulonglong2* ar = (const ulonglong2*)(sAs + r * 16);
            const ulonglong2 q0 = ar[0];
            const ulonglong2 q1 = ar[1];
            fma2(acc[0], ss, q0.x); fma2(acc[1], ss, q0.y);
            fma2(acc[2], ss, q1.x); fma2(acc[3], ss, q1.y);
            const ulonglong2 q2 = ar[2];
            const ulonglong2 q3 = ar[3];
            fma2(acc[4], ss, q2.x); fma2(acc[5], ss, q2.y);
            fma2(acc[6], ss, q3.x); fma2(acc[7], ss, q3.y);
        }
        __syncthreads();   // everyone done reading this slot

        if (tid == 0 && it + NSLOT < NITER) issue_stage(it + NSLOT);
    }

    if (c < NC) {
#pragma unroll
        for (int p = 0; p < 8; p++) {
            float blo, bhi;
            upk2(acc[p], blo, bhi);
            atomicAdd(out + (2 * p) * NC + c,     blo);
            atomicAdd(out + (2 * p + 1) * NC + c, bhi);
        }
    }
}

// ---------------------------------------------------------------------------
extern "C" void kernel_launch(void* const* d_in, const int* in_sizes, int n_in,
                              void* d_out, int out_size)
{
    const float* x     = (const float*)d_in[0];  // (2,16,512,12)
    const float* cuts  = (const float*)d_in[1];  // (12,1)
    const float* score = (const float*)d_in[2];  // (4096,1000)
    float* out = (float*)d_out;                  // (16,1000)

    leaf_kernel<<<BB * NCHUNK, 256>>>(x, cuts, out);
    dim3 g3(NL / G_LCH, (NC + G_CTW - 1) / G_CTW);   // (64, 4)
    gemm_out_kernel<<<g3, 256>>>(score, out);
}

// round 10
// speedup vs baseline: 1.0133x; 1.0133x over previous
#include <cuda_runtime.h>
#include <cstdint>

// Problem constants
#define LL 2
#define BB 16
#define TT 512
#define HH 12
#define NL 4096   // (1+1)^12 leaves
#define NC 1000
#define NCHUNK 16 // token chunks per batch
#define TOKC 32   // tokens per chunk

// GEMM tiling: 256 CTAs = (64 row-chunks) x (4 col-tiles)
#define G_LCH 64
#define G_CTW 256
#define NCTA  256

// Scratch + sync counters
__device__ float g_part[NCHUNK * BB * NL];  // [chunk][batch][leaf] (4 MB)
__device__ int gA = 0;   // leaf-done count
__device__ int gB = 0;   // exit ticket (for counter reset)

// Dynamic smem layout (bytes)
#define SM_SS 0                     // score tile: 64 * 256 * 4 = 65536
#define SM_P  65536                 // leaf products: 32*128*4 = 16384
#define SM_SX 81920                 // x slice: 32*12*4 = 1536
#define SM_SC 83456                 // cuts: 48 (padded)
#define SM_SA 83520                 // avg tile [l][b]: 64*16*4 = 4096
#define SM_MB 87616                 // mbarrier: 8
#define SMEM_TOTAL 87680

// ---- f32x2 helpers ---------------------------------------------------------
__device__ __forceinline__ unsigned long long pk2(float x, float y) {
    unsigned long long r;
    asm("mov.b64 %0, {%1, %2};" : "=l"(r) : "f"(x), "f"(y));
    return r;
}
__device__ __forceinline__ void fma2(unsigned long long& d,
                                     unsigned long long a,
                                     unsigned long long b) {
    asm("fma.rn.f32x2 %0, %1, %2, %0;" : "+l"(d) : "l"(a), "l"(b));
}
__device__ __forceinline__ void upk2(unsigned long long v, float& lo, float& hi) {
    asm("mov.b64 {%0, %1}, %2;" : "=f"(lo), "=f"(hi) : "l"(v));
}

// ---- smem/TMA/sync helpers -------------------------------------------------
__device__ __forceinline__ uint32_t smem_u32(const void* p) {
    uint32_t a;
    asm("{ .reg .u64 t; cvta.to.shared.u64 t, %1; cvt.u32.u64 %0, t; }"
        : "=r"(a) : "l"(p));
    return a;
}
__device__ __forceinline__ void mbar_init(uint32_t mbar, uint32_t count) {
    asm volatile("mbarrier.init.shared.b64 [%0], %1;" :: "r"(mbar), "r"(count)
                 : "memory");
}
__device__ __forceinline__ void mbar_expect_tx(uint32_t mbar, uint32_t bytes) {
    asm volatile("mbarrier.arrive.expect_tx.shared.b64 _, [%0], %1;"
                 :: "r"(mbar), "r"(bytes) : "memory");
}
__device__ __forceinline__ void mbar_wait(uint32_t mbar, uint32_t parity) {
    uint32_t done;
    asm volatile(
        "{\n\t"
        ".reg .pred p;\n\t"
        "mbarrier.try_wait.parity.acquire.cta.shared::cta.b64 p, [%1], %2;\n\t"
        "selp.b32 %0, 1, 0, p;\n\t"
        "}"
        : "=r"(done) : "r"(mbar), "r"(parity) : "memory");
    if (!done) {
        asm volatile(
            "{\n\t"
            ".reg .pred P1;\n\t"
            "W_%=:\n\t"
            "mbarrier.try_wait.parity.acquire.cta.shared::cta.b64 P1, [%0], %1, 0x989680;\n\t"
            "@P1 bra.uni D_%=;\n\t"
            "bra.uni W_%=;\n\t"
            "D_%=:\n\t"
            "}"
            :: "r"(mbar), "r"(parity) : "memory");
    }
}
__device__ __forceinline__ void bulk_g2s(uint32_t dst, const void* src,
                                         uint32_t bytes, uint32_t mbar) {
    asm volatile(
        "cp.async.bulk.shared::cta.global.mbarrier::complete_tx::bytes "
        "[%0], [%1], %2, [%3];"
        :: "r"(dst), "l"(src), "r"(bytes), "r"(mbar) : "memory");
}
__device__ __forceinline__ int ld_acquire(const int* p) {
    int v;
    asm volatile("ld.acquire.gpu.b32 %0, [%1];" : "=r"(v) : "l"(p));
    return v;
}

// ---------------------------------------------------------------------------
// Fused kernel: 256 CTAs, 256 threads, all co-resident (2 CTAs/SM by smem).
// Phase 0: issue full 64-row score TMA tile (overlaps everything below).
// Phase 1: leaf products for (b=blk>>4, chunk=blk&15) -> g_part; zero out.
// Phase 2: grid spin-sync on gA.
// Phase 3: reduce g_part -> sA, wait score, 64-row GEMM, split-K atomics.
// ---------------------------------------------------------------------------
__global__ void __launch_bounds__(256, 2) fused_kernel(
    const float* __restrict__ x, const float* __restrict__ cuts,
    const float* __restrict__ score, float* __restrict__ out)
{
    extern __shared__ __align__(16) char sm[];
    float* sS = (float*)(sm + SM_SS);
    float* P  = (float*)(sm + SM_P);
    float* sx = (float*)(sm + SM_SX);
    float* sc = (float*)(sm + SM_SC);
    float* sA = (float*)(sm + SM_SA);
    const uint32_t mb = smem_u32(sm + SM_MB);

    const int tid = threadIdx.x;
    const int blk = blockIdx.x;

    // GEMM tile coordinates
    const int l0 = (blk >> 2) * G_LCH;
    const int c0 = (blk & 3) * G_CTW;
    const int wbytes = (c0 + G_CTW <= NC) ? (G_CTW * 4) : ((NC - c0) * 4);

    // ---- Phase 0: queue the whole score tile via TMA bulk copies ----
    if (tid == 0) {
        mbar_init(mb, 1);
        asm volatile("fence.proxy.async.shared::cta;" ::: "memory");
        mbar_expect_tx(mb, (uint32_t)(G_LCH * wbytes));
        const char* src = (const char*)score
            + (size_t)l0 * (NC * 4) + (size_t)c0 * 4;
        const uint32_t dstb = smem_u32(sS);
#pragma unroll 4
        for (int r = 0; r < G_LCH; r++)
            bulk_g2s(dstb + (uint32_t)(r * G_CTW * 4),
                     src + (size_t)r * (NC * 4), (uint32_t)wbytes, mb);
    }

    // ---- Phase 1: leaf products ----
    const int gid = blk * 256 + tid;          // 65536 >= 16000
    if (gid < BB * NC) out[gid] = 0.f;

    const int b     = blk >> 4;
    const int chunk = blk & 15;

    if (tid < 12) sc[tid] = cuts[tid];
    const float* xl = x + (size_t)(LL - 1) * BB * TT * HH
                        + ((size_t)b * TT + (size_t)chunk * TOKC) * HH;
    for (int i = tid; i < TOKC * 12; i += 256) sx[i] = xl[i];
    __syncthreads();

    // Phase A: factorized half-leaf products (8 contiguous outputs per task)
    {
        const int half = (tid >> 3) & 1;
        const int g    = tid & 7;
        const float* cr = sc + half * 6;
        const float c0f = cr[0], c1f = cr[1], c2f = cr[2];
        const float c3f = cr[3], c4f = cr[4], c5f = cr[5];
#pragma unroll
        for (int t2 = 0; t2 < 2; t2++) {
            const int tok = (tid >> 4) + t2 * 16;
            const float* xr = sx + tok * 12 + half * 6;
            const float x0 = xr[0], x1 = xr[1], x2 = xr[2];
            const float x3 = xr[3], x4 = xr[4], x5 = xr[5];
            const float F0 = (g & 4) ? fmaf(2.f, x0, -c0f) : x0;
            const float F1 = (g & 2) ? fmaf(2.f, x1, -c1f) : x1;
            const float F2 = (g & 1) ? fmaf(2.f, x2, -c2f) : x2;
            const float p  = F0 * F1 * F2;
            const float b3 = fmaf(2.f, x3, -c3f);
            const float a4 = x4, b4 = fmaf(2.f, x4, -c4f);
            const float a5 = x5, b5 = fmaf(2.f, x5, -c5f);
            const float m00 = a4 * a5, m01 = a4 * b5;
            const float m10 = b4 * a5, m11 = b4 * b5;
            const float q0 = p * x3, q1 = p * b3;
            float* dst = P + tok * 128 + half * 64 + g * 8;
            *(float4*)dst       = make_float4(q0 * m00, q0 * m01, q0 * m10, q0 * m11);
            *(float4*)(dst + 4) = make_float4(q1 * m00, q1 * m01, q1 * m10, q1 * m11);
        }
    }
    __syncthreads();

    // Phase B: rank-1 accumulation into g_part
    {
        const int w = tid >> 5, lane = tid & 31;
        unsigned long long acc2[4][2];
#pragma unroll
        for (int p = 0; p < 4; p++) { acc2[p][0] = 0ull; acc2[p][1] = 0ull; }

#pragma unroll 4
        for (int tok = 0; tok < TOKC; tok++) {
            const float* Pr = P + tok * 128;
            const ulonglong2* ph = (const ulonglong2*)(Pr + 8 * w);
            const ulonglong2 h0 = ph[0];
            const ulonglong2 h1 = ph[1];
            const float plo0 = Pr[64 + lane];
            const float plo1 = Pr[64 + lane + 32];
            const unsigned long long pl0 = pk2(plo0, plo0);
            const unsigned long long pl1 = pk2(plo1, plo1);
            fma2(acc2[0][0], h0.x, pl0); fma2(acc2[0][1], h0.x, pl1);
            fma2(acc2[1][0], h0.y, pl0); fma2(acc2[1][1], h0.y, pl1);
            fma2(acc2[2][0], h1.x, pl0); fma2(acc2[2][1], h1.x, pl1);
            fma2(acc2[3][0], h1.y, pl0); fma2(acc2[3][1], h1.y, pl1);
        }

        const float s = 1.f / (float)TT;
        float* dst = g_part + ((size_t)(chunk * BB + b)) * NL;
#pragma unroll
        for (int p = 0; p < 4; p++) {
            float u0v0, u1v0, u0v1, u1v1;
            upk2(acc2[p][0], u0v0, u1v0);
            upk2(acc2[p][1], u0v1, u1v1);
            const int u0 = 8 * w + 2 * p;
            dst[u0 * 64 + lane]            = u0v0 * s;
            dst[u0 * 64 + lane + 32]       = u0v1 * s;
            dst[(u0 + 1) * 64 + lane]      = u1v0 * s;
            dst[(u0 + 1) * 64 + lane + 32] = u1v1 * s;
        }
    }

    // ---- Phase 2: grid-wide leaf barrier (all 256 CTAs co-resident) ----
    __threadfence();
    __syncthreads();
    if (tid == 0) {
        atomicAdd(&gA, 1);
        while (ld_acquire(&gA) < NCTA) { __nanosleep(64); }
    }
    __syncthreads();

    // ---- Phase 3a: reduce 16 chunk partials -> sA[l][b] (L2-hot) ----
    {
        const int bb = tid >> 4;          // batch 0..15
        const int lq = tid & 15;          // leaf quad 0..15
        const float4* p = (const float4*)(g_part + (size_t)bb * NL + l0) + lq;
        float4 v = make_float4(0.f, 0.f, 0.f, 0.f);
#pragma unroll
        for (int ch = 0; ch < NCHUNK; ch++) {
            const float4 t = p[(size_t)ch * (BB * NL / 4)];
            v.x += t.x; v.y += t.y; v.z += t.z; v.w += t.w;
        }
        sA[(lq * 4 + 0) * 16 + bb] = v.x;
        sA[(lq * 4 + 1) * 16 + bb] = v.y;
        sA[(lq * 4 + 2) * 16 + bb] = v.z;
        sA[(lq * 4 + 3) * 16 + bb] = v.w;
    }
    __syncthreads();

    // ---- Phase 3b: wait for the score tile (streamed since t=0) ----
    mbar_wait(mb, 0);

    // ---- Phase 3c: 64-row GEMM; thread = 1 col x 16 batches ----
    unsigned long long acc[8];
#pragma unroll
    for (int p = 0; p < 8; p++) acc[p] = 0ull;

    const int c = c0 + tid;
    const float* sSs = sS + tid;
#pragma unroll 8
    for (int r = 0; r < G_LCH; r++) {
        const float sv = sSs[r * G_CTW];
        const unsigned long long ss = pk2(sv, sv);
        const ulonglong2* ar = (const ulonglong2*)(sA + r * 16);
        const ulonglong2 q0 = ar[0];
        const ulonglong2 q1 = ar[1];
        fma2(acc[0], ss, q0.x); fma2(acc[1], ss, q0.y);
        fma2(acc[2], ss, q1.x); fma2(acc[3], ss, q1.y);
        const ulonglong2 q2 = ar[2];
        const ulonglong2 q3 = ar[3];
        fma2(acc[4], ss, q2.x); fma2(acc[5], ss, q2.y);
        fma2(acc[6], ss, q3.x); fma2(acc[7], ss, q3.y);
    }

    if (c < NC) {
#pragma unroll
        for (int p = 0; p < 8; p++) {
            float blo, bhi;
            upk2(acc[p], blo, bhi);
            atomicAdd(out + (2 * p) * NC + c,     blo);
            atomicAdd(out + (2 * p + 1) * NC + c, bhi);
        }
    }

    // ---- Reset counters for next (graph-replayed) launch ----
    __syncthreads();
    if (tid == 0) {
        const int t = atomicAdd(&gB, 1);
        if (t == NCTA - 1) {
            atomicExch(&gB, 0);
            atomicExch(&gA, 0);
        }
    }
}

// ---------------------------------------------------------------------------
extern "C" void kernel_launch(void* const* d_in, const int* in_sizes, int n_in,
                              void* d_out, int out_size)
{
    const float* x     = (const float*)d_in[0];  // (2,16,512,12)
    const float* cuts  = (const float*)d_in[1];  // (12,1)
    const float* score = (const float*)d_in[2];  // (4096,1000)
    float* out = (float*)d_out;                  // (16,1000)

    static bool attr_set = false;
    if (!attr_set) {
        cudaFuncSetAttribute(fused_kernel,
                             cudaFuncAttributeMaxDynamicSharedMemorySize,
                             SMEM_TOTAL);
        attr_set = true;
    }
    fused_kernel<<<NCTA, 256, SMEM_TOTAL>>>(x, cuts, score, out);
}

// round 11
// speedup vs baseline: 1.0288x; 1.0152x over previous
#include <cuda_runtime.h>
#include <cstdint>

// Problem constants
#define LL 2
#define BB 16
#define TT 512
#define HH 12
#define NL 4096   // (1+1)^12 leaves
#define NC 1000
#define NCHUNK 16 // token chunks per batch
#define TOKC 32   // tokens per chunk

// GEMM tiling: 256 CTAs = (64 row-chunks) x (4 col-tiles)
#define G_LCH 64
#define G_CTW 256
#define NCTA  256
#define R_STG 16                    // rows per pipeline stage
#define NSTG  (G_LCH / R_STG)       // 4 stages

// Scratch + sync counters
__device__ float g_part[NCHUNK * BB * NL];  // [chunk][batch][leaf] (4 MB)
__device__ int gA = 0;   // leaf-done count
__device__ int gB = 0;   // exit ticket (for counter reset)

// Dynamic smem layout (bytes)
#define SM_SS 0                     // score tile: 64 * 256 * 4 = 65536
#define SM_P  65536                 // leaf products: 32*128*4 = 16384
#define SM_SX 81920                 // x slice: 32*12*4 = 1536
#define SM_SC 83456                 // cuts: 64
#define SM_SA 83520                 // avg tile [l][b]: 64*16*4 = 4096
#define SM_MB 87616                 // mbarriers: 4 * 8 = 32
#define SMEM_TOTAL 87680

// ---- f32x2 helpers ---------------------------------------------------------
__device__ __forceinline__ unsigned long long pk2(float x, float y) {
    unsigned long long r;
    asm("mov.b64 %0, {%1, %2};" : "=l"(r) : "f"(x), "f"(y));
    return r;
}
__device__ __forceinline__ void fma2(unsigned long long& d,
                                     unsigned long long a,
                                     unsigned long long b) {
    asm("fma.rn.f32x2 %0, %1, %2, %0;" : "+l"(d) : "l"(a), "l"(b));
}
__device__ __forceinline__ void upk2(unsigned long long v, float& lo, float& hi) {
    asm("mov.b64 {%0, %1}, %2;" : "=f"(lo), "=f"(hi) : "l"(v));
}

// ---- smem/TMA/sync helpers -------------------------------------------------
__device__ __forceinline__ uint32_t smem_u32(const void* p) {
    uint32_t a;
    asm("{ .reg .u64 t; cvta.to.shared.u64 t, %1; cvt.u32.u64 %0, t; }"
        : "=r"(a) : "l"(p));
    return a;
}
__device__ __forceinline__ void mbar_init(uint32_t mbar, uint32_t count) {
    asm volatile("mbarrier.init.shared.b64 [%0], %1;" :: "r"(mbar), "r"(count)
                 : "memory");
}
__device__ __forceinline__ void mbar_expect_tx(uint32_t mbar, uint32_t bytes) {
    asm volatile("mbarrier.arrive.expect_tx.shared.b64 _, [%0], %1;"
                 :: "r"(mbar), "r"(bytes) : "memory");
}
__device__ __forceinline__ void mbar_wait(uint32_t mbar, uint32_t parity) {
    uint32_t done;
    asm volatile(
        "{\n\t"
        ".reg .pred p;\n\t"
        "mbarrier.try_wait.parity.acquire.cta.shared::cta.b64 p, [%1], %2;\n\t"
        "selp.b32 %0, 1, 0, p;\n\t"
        "}"
        : "=r"(done) : "r"(mbar), "r"(parity) : "memory");
    if (!done) {
        asm volatile(
            "{\n\t"
            ".reg .pred P1;\n\t"
            "W_%=:\n\t"
            "mbarrier.try_wait.parity.acquire.cta.shared::cta.b64 P1, [%0], %1, 0x989680;\n\t"
            "@P1 bra.uni D_%=;\n\t"
            "bra.uni W_%=;\n\t"
            "D_%=:\n\t"
            "}"
            :: "r"(mbar), "r"(parity) : "memory");
    }
}
__device__ __forceinline__ void bulk_g2s(uint32_t dst, const void* src,
                                         uint32_t bytes, uint32_t mbar) {
    asm volatile(
        "cp.async.bulk.shared::cta.global.mbarrier::complete_tx::bytes "
        "[%0], [%1], %2, [%3];"
        :: "r"(dst), "l"(src), "r"(bytes), "r"(mbar) : "memory");
}
__device__ __forceinline__ int ld_acquire(const int* p) {
    int v;
    asm volatile("ld.acquire.gpu.b32 %0, [%1];" : "=r"(v) : "l"(p));
    return v;
}

// ---------------------------------------------------------------------------
// Fused persistent kernel: 256 CTAs x 256 threads, all co-resident.
// Phase 0: issue 4 staged TMA bulk-copy groups for this CTA's score tile.
// Phase 1: leaf products -> g_part (overlaps score stream).
// Phase 2: grid spin-sync.
// Phase 3: reduce g_part -> sA, then per-stage {mbar wait, 16-row GEMM},
//          split-K float atomics into out.
// ---------------------------------------------------------------------------
__global__ void __launch_bounds__(256, 2) fused_kernel(
    const float* __restrict__ x, const float* __restrict__ cuts,
    const float* __restrict__ score, float* __restrict__ out)
{
    extern __shared__ __align__(16) char sm[];
    float* sS = (float*)(sm + SM_SS);
    float* P  = (float*)(sm + SM_P);
    float* sx = (float*)(sm + SM_SX);
    float* sc = (float*)(sm + SM_SC);
    float* sA = (float*)(sm + SM_SA);
    const uint32_t mb0 = smem_u32(sm + SM_MB);

    const int tid = threadIdx.x;
    const int blk = blockIdx.x;

    // GEMM tile coordinates
    const int l0 = (blk >> 2) * G_LCH;
    const int c0 = (blk & 3) * G_CTW;
    const int wbytes = (c0 + G_CTW <= NC) ? (G_CTW * 4) : ((NC - c0) * 4);

    // ---- Phase 0: init mbarriers, then issue 4 TMA stages in parallel ----
    if (tid == 0) {
#pragma unroll
        for (int s = 0; s < NSTG; s++) mbar_init(mb0 + 8 * s, 1);
        asm volatile("fence.proxy.async.shared::cta;" ::: "memory");
    }
    __syncthreads();

    if (tid < NSTG) {
        const int s = tid;
        const uint32_t mb = mb0 + 8 * s;
        mbar_expect_tx(mb, (uint32_t)(R_STG * wbytes));
        const char* src = (const char*)score
            + (size_t)(l0 + s * R_STG) * (NC * 4) + (size_t)c0 * 4;
        const uint32_t dstb = smem_u32(sS) + (uint32_t)(s * R_STG * G_CTW * 4);
#pragma unroll
        for (int r = 0; r < R_STG; r++)
            bulk_g2s(dstb + (uint32_t)(r * G_CTW * 4),
                     src + (size_t)r * (NC * 4), (uint32_t)wbytes, mb);
    }

    // ---- Phase 1: leaf products ----
    const int gid = blk * 256 + tid;          // 65536 >= 16000
    if (gid < BB * NC) out[gid] = 0.f;

    const int b     = blk >> 4;
    const int chunk = blk & 15;

    if (tid < 12) sc[tid] = cuts[tid];
    const float* xl = x + (size_t)(LL - 1) * BB * TT * HH
                        + ((size_t)b * TT + (size_t)chunk * TOKC) * HH;
    for (int i = tid; i < TOKC * 12; i += 256) sx[i] = xl[i];
    __syncthreads();

    // Phase A: factorized half-leaf products
    {
        const int half = (tid >> 3) & 1;
        const int g    = tid & 7;
        const float* cr = sc + half * 6;
        const float c0f = cr[0], c1f = cr[1], c2f = cr[2];
        const float c3f = cr[3], c4f = cr[4], c5f = cr[5];
#pragma unroll
        for (int t2 = 0; t2 < 2; t2++) {
            const int tok = (tid >> 4) + t2 * 16;
            const float* xr = sx + tok * 12 + half * 6;
            const float x0 = xr[0], x1 = xr[1], x2 = xr[2];
            const float x3 = xr[3], x4 = xr[4], x5 = xr[5];
            const float F0 = (g & 4) ? fmaf(2.f, x0, -c0f) : x0;
            const float F1 = (g & 2) ? fmaf(2.f, x1, -c1f) : x1;
            const float F2 = (g & 1) ? fmaf(2.f, x2, -c2f) : x2;
            const float p  = F0 * F1 * F2;
            const float b3 = fmaf(2.f, x3, -c3f);
            const float a4 = x4, b4 = fmaf(2.f, x4, -c4f);
            const float a5 = x5, b5 = fmaf(2.f, x5, -c5f);
            const float m00 = a4 * a5, m01 = a4 * b5;
            const float m10 = b4 * a5, m11 = b4 * b5;
            const float q0 = p * x3, q1 = p * b3;
            float* dst = P + tok * 128 + half * 64 + g * 8;
            *(float4*)dst       = make_float4(q0 * m00, q0 * m01, q0 * m10, q0 * m11);
            *(float4*)(dst + 4) = make_float4(q1 * m00, q1 * m01, q1 * m10, q1 * m11);
        }
    }
    __syncthreads();

    // Phase B: rank-1 accumulation into g_part
    {
        const int w = tid >> 5, lane = tid & 31;
        unsigned long long acc2[4][2];
#pragma unroll
        for (int p = 0; p < 4; p++) { acc2[p][0] = 0ull; acc2[p][1] = 0ull; }

#pragma unroll 4
        for (int tok = 0; tok < TOKC; tok++) {
            const float* Pr = P + tok * 128;
            const ulonglong2* ph = (const ulonglong2*)(Pr + 8 * w);
            const ulonglong2 h0 = ph[0];
            const ulonglong2 h1 = ph[1];
            const float plo0 = Pr[64 + lane];
            const float plo1 = Pr[64 + lane + 32];
            const unsigned long long pl0 = pk2(plo0, plo0);
            const unsigned long long pl1 = pk2(plo1, plo1);
            fma2(acc2[0][0], h0.x, pl0); fma2(acc2[0][1], h0.x, pl1);
            fma2(acc2[1][0], h0.y, pl0); fma2(acc2[1][1], h0.y, pl1);
            fma2(acc2[2][0], h1.x, pl0); fma2(acc2[2][1], h1.x, pl1);
            fma2(acc2[3][0], h1.y, pl0); fma2(acc2[3][1], h1.y, pl1);
        }

        const float s = 1.f / (float)TT;
        float* dst = g_part + ((size_t)(chunk * BB + b)) * NL;
#pragma unroll
        for (int p = 0; p < 4; p++) {
            float u0v0, u1v0, u0v1, u1v1;
            upk2(acc2[p][0], u0v0, u1v0);
            upk2(acc2[p][1], u0v1, u1v1);
            const int u0 = 8 * w + 2 * p;
            dst[u0 * 64 + lane]            = u0v0 * s;
            dst[u0 * 64 + lane + 32]       = u0v1 * s;
            dst[(u0 + 1) * 64 + lane]      = u1v0 * s;
            dst[(u0 + 1) * 64 + lane + 32] = u1v1 * s;
        }
    }

    // ---- Phase 2: grid-wide leaf barrier (all 256 CTAs co-resident) ----
    __threadfence();
    __syncthreads();
    if (tid == 0) {
        atomicAdd(&gA, 1);
        while (ld_acquire(&gA) < NCTA) { __nanosleep(64); }
    }
    __syncthreads();

    // ---- Phase 3a: reduce 16 chunk partials -> sA[l][b] (L2-hot) ----
    {
        const int bb = tid >> 4;          // batch 0..15
        const int lq = tid & 15;          // leaf quad 0..15
        const float4* p = (const float4*)(g_part + (size_t)bb * NL + l0) + lq;
        float4 v = make_float4(0.f, 0.f, 0.f, 0.f);
#pragma unroll
        for (int ch = 0; ch < NCHUNK; ch++) {
            const float4 t = p[(size_t)ch * (BB * NL / 4)];
            v.x += t.x; v.y += t.y; v.z += t.z; v.w += t.w;
        }
        sA[(lq * 4 + 0) * 16 + bb] = v.x;
        sA[(lq * 4 + 1) * 16 + bb] = v.y;
        sA[(lq * 4 + 2) * 16 + bb] = v.z;
        sA[(lq * 4 + 3) * 16 + bb] = v.w;
    }
    __syncthreads();

    // ---- Phase 3b: staged GEMM — consume each 16-row stage as it lands ----
    unsigned long long acc[8];
#pragma unroll
    for (int p = 0; p < 8; p++) acc[p] = 0ull;

    const int c = c0 + tid;
    const float* sSs = sS + tid;

#pragma unroll
    for (int s = 0; s < NSTG; s++) {
        mbar_wait(mb0 + 8 * s, 0);
        const float* sAs = sA + (s * R_STG) * 16;
#pragma unroll
        for (int r = 0; r < R_STG; r++) {
            const float sv = sSs[(s * R_STG + r) * G_CTW];
            const unsigned long long ss = pk2(sv, sv);
            const ulonglong2* ar = (const ulonglong2*)(sAs + r * 16);
            const ulonglong2 q0 = ar[0];
            const ulonglong2 q1 = ar[1];
            fma2(acc[0], ss, q0.x); fma2(acc[1], ss, q0.y);
            fma2(acc[2], ss, q1.x); fma2(acc[3], ss, q1.y);
            const ulonglong2 q2 = ar[2];
            const ulonglong2 q3 = ar[3];
            fma2(acc[4], ss, q2.x); fma2(acc[5], ss, q2.y);
            fma2(acc[6], ss, q3.x); fma2(acc[7], ss, q3.y);
        }
    }

    if (c < NC) {
#pragma unroll
        for (int p = 0; p < 8; p++) {
            float blo, bhi;
            upk2(acc[p], blo, bhi);
            atomicAdd(out + (2 * p) * NC + c,     blo);
            atomicAdd(out + (2 * p + 1) * NC + c, bhi);
        }
    }

    // ---- Reset counters for next (graph-replayed) launch ----
    __syncthreads();
    if (tid == 0) {
        const int t = atomicAdd(&gB, 1);
        if (t == NCTA - 1) {
            atomicExch(&gB, 0);
            atomicExch(&gA, 0);
        }
    }
}

// ---------------------------------------------------------------------------
extern "C" void kernel_launch(void* const* d_in, const int* in_sizes, int n_in,
                              void* d_out, int out_size)
{
    const float* x     = (const float*)d_in[0];  // (2,16,512,12)
    const float* cuts  = (const float*)d_in[1];  // (12,1)
    const float* score = (const float*)d_in[2];  // (4096,1000)
    float* out = (float*)d_out;                  // (16,1000)

    static bool attr_set = false;
    if (!attr_set) {
        cudaFuncSetAttribute(fused_kernel,
                             cudaFuncAttributeMaxDynamicSharedMemorySize,
                             SMEM_TOTAL);
        attr_set = true;
    }
    fused_kernel<<<NCTA, 256, SMEM_TOTAL>>>(x, cuts, score, out);
}